// round 5
// baseline (speedup 1.0000x reference)
#include <cuda_runtime.h>

#define IN_DIM  4096
#define OUT_DIM 4096
#define BATCH   16384
#define THREADS 512
#define CPT     8              // columns per thread (OUT_DIM / THREADS)
#define ROWS_PER_BLOCK 16

// Packed per-output-column parameters (filled by precompute kernel)
__device__ float4 g_coef[OUT_DIM];
__device__ int2   g_idx[OUT_DIM];

// GATE_COEFS (16 gates x 4 coefficients)
__constant__ float G[16][4] = {
    {0, 0, 0, 0},  {0, 0, 0, 1},  {0, 1, 0,-1},  {0, 1, 0, 0},
    {0, 0, 1,-1},  {0, 0, 1, 0},  {0, 1, 1,-2},  {0, 1, 1,-1},
    {1,-1,-1, 1},  {1,-1,-1, 2},  {1, 0,-1, 0},  {1, 0,-1, 1},
    {1,-1, 0, 0},  {1,-1, 0, 1},  {1, 0, 0,-1},  {1, 0, 0, 0}
};

// idx buffers may be int32 or int64 depending on the harness's JAX x64 config.
// For int64-encoded indices in [0, IN_DIM), every odd 32-bit word is zero.
// For int32, odd words are random indices (all-zero probability ~ (1/4096)^4).
__device__ __forceinline__ int read_idx(const int* p32, int j, bool is64)
{
    return is64 ? p32[2 * j] : p32[j];
}

__global__ void precompute_kernel(const float* __restrict__ w,
                                  const int* __restrict__ ia32,
                                  const int* __restrict__ ib32)
{
    int j = blockIdx.x * blockDim.x + threadIdx.x;
    if (j >= OUT_DIM) return;

    // dtype sniff (uniform across all threads -> no divergence)
    const bool ia_is64 = ((ia32[1] | ia32[3] | ia32[5] | ia32[7]) == 0);
    const bool ib_is64 = ((ib32[1] | ib32[3] | ib32[5] | ib32[7]) == 0);

    float wv[16];
    float m = -1e30f;
#pragma unroll
    for (int k = 0; k < 16; k++) { wv[k] = w[j * 16 + k]; m = fmaxf(m, wv[k]); }
    float s = 0.f;
#pragma unroll
    for (int k = 0; k < 16; k++) { wv[k] = __expf(wv[k] - m); s += wv[k]; }
    float inv = 1.0f / s;
    float c0 = 0.f, c1 = 0.f, c2 = 0.f, c3 = 0.f;
#pragma unroll
    for (int k = 0; k < 16; k++) {
        float p = wv[k] * inv;
        c0 += p * G[k][0];
        c1 += p * G[k][1];
        c2 += p * G[k][2];
        c3 += p * G[k][3];
    }
    g_coef[j] = make_float4(c0, c1, c2, c3);

    int a = read_idx(ia32, j, ia_is64);
    int b = read_idx(ib32, j, ib_is64);
    // safety clamp (also guards a misdetect from producing OOB smem reads)
    a &= (IN_DIM - 1);
    b &= (IN_DIM - 1);
    g_idx[j] = make_int2(a, b);
}

__global__ __launch_bounds__(THREADS, 1)
void logic_kernel(const float* __restrict__ x, float* __restrict__ y)
{
    __shared__ float row[2][IN_DIM];   // 2 x 16KB double buffer

    const int t    = threadIdx.x;
    const int row0 = blockIdx.x * ROWS_PER_BLOCK;

    // Per-thread column parameters: held in registers for the whole block.
    // Thread t owns consecutive columns [t*CPT, t*CPT+CPT) -> vectorized STG.
    float4 coef[CPT];
    int2   idx[CPT];
#pragma unroll
    for (int k = 0; k < CPT; k++) {
        coef[k] = g_coef[t * CPT + k];
        idx[k]  = g_idx[t * CPT + k];
    }

    // Prefetch first row into registers (coalesced float4: 1024 float4 / 512 thr)
    float4 pre0, pre1;
    {
        const float4* xr = (const float4*)(x + (size_t)row0 * IN_DIM);
        pre0 = xr[t];
        pre1 = xr[t + THREADS];
    }

    for (int r = 0; r < ROWS_PER_BLOCK; r++) {
        const int buf = r & 1;
        // Commit prefetched row to smem
        ((float4*)row[buf])[t]           = pre0;
        ((float4*)row[buf])[t + THREADS] = pre1;

        // Issue next row's global loads early (overlap with compute below)
        if (r + 1 < ROWS_PER_BLOCK) {
            const float4* xn = (const float4*)(x + (size_t)(row0 + r + 1) * IN_DIM);
            pre0 = xn[t];
            pre1 = xn[t + THREADS];
        }
        __syncthreads();

        const float* rw = row[buf];
        float out[CPT];
#pragma unroll
        for (int k = 0; k < CPT; k++) {
            float a = rw[idx[k].x];
            float b = rw[idx[k].y];
            // c0 + c1*a + c2*b + c3*a*b  ==  c0 + a*(c1 + c3*b) + c2*b
            out[k] = coef[k].x + a * (coef[k].y + coef[k].w * b) + coef[k].z * b;
        }

        float4* yo = (float4*)(y + (size_t)(row0 + r) * OUT_DIM + t * CPT);
        yo[0] = make_float4(out[0], out[1], out[2], out[3]);
        yo[1] = make_float4(out[4], out[5], out[6], out[7]);
        // No trailing sync needed: next iteration writes the *other* buffer,
        // and the sync at the top of iteration r+1 (which follows this
        // compute in program order for every warp) protects buffer reuse at r+2.
    }
}

extern "C" void kernel_launch(void* const* d_in, const int* in_sizes, int n_in,
                              void* d_out, int out_size)
{
    const float* x  = (const float*)d_in[0];
    const float* w  = (const float*)d_in[1];
    const int*   ia = (const int*)d_in[2];
    const int*   ib = (const int*)d_in[3];
    float*       y  = (float*)d_out;

    precompute_kernel<<<OUT_DIM / 256, 256>>>(w, ia, ib);
    logic_kernel<<<BATCH / ROWS_PER_BLOCK, THREADS>>>(x, y);
}

// round 6
// speedup vs baseline: 1.3783x; 1.3783x over previous
#include <cuda_runtime.h>

#define IN_DIM  4096
#define OUT_DIM 4096
#define BATCH   16384
#define THREADS 1024
#define CPT     4              // columns per thread (OUT_DIM / THREADS)
#define ROWS_PER_BLOCK 16

// Packed per-output-column parameters (filled by precompute kernel)
__device__ float4 g_coef[OUT_DIM];
__device__ int2   g_idx[OUT_DIM];

// GATE_COEFS (16 gates x 4 coefficients)
__constant__ float G[16][4] = {
    {0, 0, 0, 0},  {0, 0, 0, 1},  {0, 1, 0,-1},  {0, 1, 0, 0},
    {0, 0, 1,-1},  {0, 0, 1, 0},  {0, 1, 1,-2},  {0, 1, 1,-1},
    {1,-1,-1, 1},  {1,-1,-1, 2},  {1, 0,-1, 0},  {1, 0,-1, 1},
    {1,-1, 0, 0},  {1,-1, 0, 1},  {1, 0, 0,-1},  {1, 0, 0, 0}
};

// idx buffers may be int32 or int64 depending on the harness's JAX x64 config.
// For int64-encoded indices in [0, IN_DIM), every odd 32-bit word is zero.
// For int32, odd words are random indices (all-zero probability ~ (1/4096)^4).
__device__ __forceinline__ int read_idx(const int* p32, int j, bool is64)
{
    return is64 ? p32[2 * j] : p32[j];
}

__global__ void precompute_kernel(const float* __restrict__ w,
                                  const int* __restrict__ ia32,
                                  const int* __restrict__ ib32)
{
    int j = blockIdx.x * blockDim.x + threadIdx.x;
    if (j >= OUT_DIM) return;

    // dtype sniff (uniform across all threads -> no divergence)
    const bool ia_is64 = ((ia32[1] | ia32[3] | ia32[5] | ia32[7]) == 0);
    const bool ib_is64 = ((ib32[1] | ib32[3] | ib32[5] | ib32[7]) == 0);

    float wv[16];
    float m = -1e30f;
#pragma unroll
    for (int k = 0; k < 16; k++) { wv[k] = w[j * 16 + k]; m = fmaxf(m, wv[k]); }
    float s = 0.f;
#pragma unroll
    for (int k = 0; k < 16; k++) { wv[k] = __expf(wv[k] - m); s += wv[k]; }
    float inv = 1.0f / s;
    float c0 = 0.f, c1 = 0.f, c2 = 0.f, c3 = 0.f;
#pragma unroll
    for (int k = 0; k < 16; k++) {
        float p = wv[k] * inv;
        c0 += p * G[k][0];
        c1 += p * G[k][1];
        c2 += p * G[k][2];
        c3 += p * G[k][3];
    }
    g_coef[j] = make_float4(c0, c1, c2, c3);

    int a = read_idx(ia32, j, ia_is64);
    int b = read_idx(ib32, j, ib_is64);
    // safety clamp (also guards a misdetect from producing OOB smem reads)
    a &= (IN_DIM - 1);
    b &= (IN_DIM - 1);
    g_idx[j] = make_int2(a, b);
}

__global__ __launch_bounds__(THREADS, 1)
void logic_kernel(const float* __restrict__ x, float* __restrict__ y)
{
    __shared__ float row[2][IN_DIM];   // 2 x 16KB double buffer

    const int t    = threadIdx.x;
    const int row0 = blockIdx.x * ROWS_PER_BLOCK;

    // Per-thread column parameters: held in registers for the whole block.
    // Thread t owns consecutive columns [t*CPT, t*CPT+CPT) -> one STG.128.
    float4 coef[CPT];
    int2   idx[CPT];
#pragma unroll
    for (int k = 0; k < CPT; k++) {
        coef[k] = g_coef[t * CPT + k];
        idx[k]  = g_idx[t * CPT + k];
    }

    // Prefetch first row into a register (coalesced: 1024 float4 / 1024 thr)
    float4 pre;
    {
        const float4* xr = (const float4*)(x + (size_t)row0 * IN_DIM);
        pre = xr[t];
    }

    for (int r = 0; r < ROWS_PER_BLOCK; r++) {
        const int buf = r & 1;
        // Commit prefetched row to smem
        ((float4*)row[buf])[t] = pre;

        // Issue next row's global load early (overlaps with compute below)
        if (r + 1 < ROWS_PER_BLOCK) {
            const float4* xn = (const float4*)(x + (size_t)(row0 + r + 1) * IN_DIM);
            pre = xn[t];
        }
        __syncthreads();

        const float* rw = row[buf];
        float out[CPT];
#pragma unroll
        for (int k = 0; k < CPT; k++) {
            float a = rw[idx[k].x];
            float b = rw[idx[k].y];
            // c0 + c1*a + c2*b + c3*a*b  ==  c0 + a*(c1 + c3*b) + c2*b
            out[k] = coef[k].x + a * (coef[k].y + coef[k].w * b) + coef[k].z * b;
        }

        float4* yo = (float4*)(y + (size_t)(row0 + r) * OUT_DIM + t * CPT);
        yo[0] = make_float4(out[0], out[1], out[2], out[3]);
        // No trailing sync needed: next iteration writes the *other* buffer,
        // and the sync at the top of iteration r+1 (which follows this
        // compute in program order for every warp) protects buffer reuse at r+2.
    }
}

extern "C" void kernel_launch(void* const* d_in, const int* in_sizes, int n_in,
                              void* d_out, int out_size)
{
    const float* x  = (const float*)d_in[0];
    const float* w  = (const float*)d_in[1];
    const int*   ia = (const int*)d_in[2];
    const int*   ib = (const int*)d_in[3];
    float*       y  = (float*)d_out;

    precompute_kernel<<<OUT_DIM / 256, 256>>>(w, ia, ib);
    logic_kernel<<<BATCH / ROWS_PER_BLOCK, THREADS>>>(x, y);
}